// round 10
// baseline (speedup 1.0000x reference)
#include <cuda_runtime.h>
#include <cuda_bf16.h>
#include <cstdint>
#include <math.h>

// Problem dims
#define B_ 32
#define L_ 64
#define E_ 512
#define U_ 512
#define V_ 32000
#define KEEPP 0.7f

// ---------------- static device scratch (no runtime allocation) ----------------
__device__ float  g_word_mask[B_*E_];          // [b][e]
__device__ float4 g_rm4[U_*B_];                // [u][b] -> 4 gate masks
__device__ float  g_fin[B_*L_*U_];             // [b*64+t][u]
__device__ float4 g_Wr4[U_*U_];                // [u][v] -> {W[u][g*512+v]}_g
__device__ float4 g_hmA[U_*B_];                // masked h ping
__device__ float4 g_hmB[U_*B_];                // masked h pong
__device__ float  g_zt[2048*2048];             // z_in gate-packed: ((t*512+v)*32+b)*4+g
__device__ unsigned g_bar[64];                 // grid barrier counters
__device__ int    g_is64;

// bf16 split operands for tensor-core GEMMs
__device__ __nv_bfloat16 g_Bth[(size_t)V_*512];   // W_out^T hi  [32000,512]
__device__ __nv_bfloat16 g_Btl[(size_t)V_*512];   // W_out^T lo
__device__ __nv_bfloat16 g_Wth[2048*512];         // W_in^T hi   [2048,512]
__device__ __nv_bfloat16 g_Wtl[2048*512];         // W_in^T lo
__device__ __nv_bfloat16 g_Ah[2048*512];          // A hi (x, later rnn)
__device__ __nv_bfloat16 g_Al[2048*512];          // A lo

// ---------------- threefry2x32, matches JAX exactly ----------------
__host__ __device__ __forceinline__ void tf2x32(uint32_t k0, uint32_t k1,
                                                uint32_t x0, uint32_t x1,
                                                uint32_t* o0, uint32_t* o1) {
  uint32_t ks2 = 0x1BD11BDAu ^ k0 ^ k1;
  uint32_t v0 = x0 + k0, v1 = x1 + k1;
#define TFR(r) { v0 += v1; v1 = (v1 << (r)) | (v1 >> (32 - (r))); v1 ^= v0; }
  TFR(13) TFR(15) TFR(26) TFR(6)  v0 += k1;  v1 += ks2 + 1u;
  TFR(17) TFR(29) TFR(16) TFR(24) v0 += ks2; v1 += k0 + 2u;
  TFR(13) TFR(15) TFR(26) TFR(6)  v0 += k0;  v1 += k1 + 3u;
  TFR(17) TFR(29) TFR(16) TFR(24) v0 += k1;  v1 += ks2 + 4u;
  TFR(13) TFR(15) TFR(26) TFR(6)  v0 += ks2; v1 += k0 + 5u;
#undef TFR
  *o0 = v0; *o1 = v1;
}

__device__ __forceinline__ float bern_val(uint32_t ka, uint32_t kb, uint32_t idx) {
  uint32_t a, b;
  tf2x32(ka, kb, 0u, idx, &a, &b);
  uint32_t bits = a ^ b;
  float u = __uint_as_float((bits >> 9) | 0x3f800000u) - 1.0f;
  return (u < KEEPP) ? (1.0f / KEEPP) : 0.0f;
}

__device__ __forceinline__ void split_bf16(float v, __nv_bfloat16* h, __nv_bfloat16* l) {
  __nv_bfloat16 hh = __float2bfloat16(v);
  *h = hh;
  *l = __float2bfloat16(v - __bfloat162float(hh));
}

// ---------------- small kernels ----------------
__global__ void detect_kernel(const int* __restrict__ tw) {
  __shared__ int s;
  if (threadIdx.x == 0) s = 0;
  __syncthreads();
  int any = 0;
  for (int i = threadIdx.x; i < 1024; i += blockDim.x) any |= tw[2*i + 1];
  if (any) atomicOr(&s, 1);
  __syncthreads();
  if (threadIdx.x == 0) g_is64 = (s == 0) ? 1 : 0;
}

// masks + W_rec repack + barrier reset + h0 init, all fused
__global__ void masks_kernel(uint32_t k1a, uint32_t k1b, uint32_t k2a, uint32_t k2b,
                             uint32_t k3a, uint32_t k3b,
                             const float* __restrict__ W_rec) {
  uint32_t idx = blockIdx.x * blockDim.x + threadIdx.x;   // exactly 1048576 threads
  if (idx < 64u) g_bar[idx] = 0u;
  if (idx < (uint32_t)(B_*E_)) g_word_mask[idx] = bern_val(k1a, k1b, idx);
  if (idx < (uint32_t)(4*B_*U_)) {
    uint32_t g = idx >> 14, b = (idx >> 9) & 31u, u = idx & 511u;
    ((float*)g_rm4)[(u*32u + b)*4u + g] = bern_val(k2a, k2b, idx);
  }
  if (idx < (uint32_t)(U_*B_))
    g_hmA[idx] = make_float4(0.f, 0.f, 0.f, 0.f);
  if (idx < 262144u) {
    int v = idx & 511, u = idx >> 9;
    const float* r = W_rec + (size_t)u * 2048 + v;
    g_Wr4[u*512 + v] = make_float4(r[0], r[512], r[1024], r[1536]);
  }
  g_fin[idx] = bern_val(k3a, k3b, idx);
}

// embedding + word dropout -> bf16 hi/lo A operand directly
__global__ void embed_kernel(const float* __restrict__ images_emb,
                             const void* __restrict__ targets,
                             const float* __restrict__ emb_table) {
  int idx = blockIdx.x * blockDim.x + threadIdx.x;        // 1048576
  int e = idx & 511, t = (idx >> 9) & 63, b = idx >> 15;
  float v;
  if (t == 0) {
    v = images_emb[b*E_ + e];
  } else {
    int w;
    if (g_is64) w = (int)((const long long*)targets)[b*L_ + (t-1)];
    else        w = ((const int*)targets)[b*L_ + (t-1)];
    v = emb_table[(size_t)w * E_ + e] * g_word_mask[b*E_ + e];
  }
  split_bf16(v, &g_Ah[idx], &g_Al[idx]);
}

// transpose [512, N] fp32 -> [N, 512] bf16 hi/lo
__global__ void transpose_split_kernel(const float* __restrict__ in,
                                       __nv_bfloat16* __restrict__ oh,
                                       __nv_bfloat16* __restrict__ ol, int N) {
  __shared__ float tile[32][33];
  int tx = threadIdx.x, ty = threadIdx.y;
  int n0 = blockIdx.x * 32, k0 = blockIdx.y * 32;
#pragma unroll
  for (int j = ty; j < 32; j += 8)
    tile[j][tx] = in[(size_t)(k0 + j) * N + n0 + tx];
  __syncthreads();
#pragma unroll
  for (int j = ty; j < 32; j += 8) {
    float v = tile[tx][j];
    size_t o = (size_t)(n0 + j) * 512 + k0 + tx;
    split_bf16(v, &oh[o], &ol[o]);
  }
}

// ---------------- persistent LSTM: all 64 steps in one kernel ----------------
// 128 blocks x 128 threads; block owns v in [4*bid, 4*bid+4); thread = (vl, b).
// W slice in smem; cell state + rec-mask in regs; grid barrier per step.
// Cross-block h-state MUST be read with ld.cg (L1 is not coherent across SMs
// within one launch on sm_103a).
__global__ __launch_bounds__(128) void lstm_persist_kernel() {
  extern __shared__ float4 sm4[];
  float4* ws4   = sm4;                       // [u][vl] : 2048 float4 = 32KB
  float*  rnn_s = (float*)(sm4 + 2048);      // [t][vl][b] : 8192 floats = 32KB

  int tid = threadIdx.x, b = tid & 31, vl = tid >> 5;
  int bid = blockIdx.x;
  int v = (bid << 2) + vl;

  for (int i = tid; i < 2048; i += 128) {
    int u = i >> 2, w = i & 3;
    ws4[i] = g_Wr4[u*512 + (bid << 2) + w];
  }
  float4 m = g_rm4[v*32 + b];
  float c = 0.f;
  __syncthreads();

  for (int t = 0; t < 64; t++) {
    const float4* __restrict__ hin = (t & 1) ? g_hmB : g_hmA;
    float4* __restrict__ hout      = (t & 1) ? g_hmA : g_hmB;

    float ax = 0.f, ay = 0.f, az = 0.f, aw = 0.f;
    const float4* hp = hin + b;
    const float4* wp = ws4 + vl;
#pragma unroll 8
    for (int u = 0; u < 512; u++) {
      float4 h4 = __ldcg(hp + u*32);       // L2-only: coherent across blocks
      float4 w4 = wp[u*4];
      ax = fmaf(h4.x, w4.x, ax);
      ay = fmaf(h4.y, w4.y, ay);
      az = fmaf(h4.z, w4.z, az);
      aw = fmaf(h4.w, w4.w, aw);
    }

    float4 z4 = *(const float4*)&g_zt[(((t << 9) + v) * 32 + b) * 4];
    float zi = z4.x + ax, zf = z4.y + ay, zg = z4.z + az, zo = z4.w + aw;

    float ig = 1.f / (1.f + expf(-zi));
    float fg = 1.f / (1.f + expf(-zf));
    float gv = tanhf(zg);
    float og = 1.f / (1.f + expf(-zo));

    c = fmaf(fg, c, ig * gv);
    float hn = og * tanhf(c);

    rnn_s[t*128 + vl*32 + b] = hn;
    hout[v*32 + b] = make_float4(hn*m.x, hn*m.y, hn*m.z, hn*m.w);

    if (t < 63) {  // grid barrier (not needed after last step)
      __threadfence();
      __syncthreads();
      if (tid == 0) {
        atomicAdd(&g_bar[t], 1u);
        while (atomicAdd(&g_bar[t], 0u) < (unsigned)gridDim.x) __nanosleep(64);
        __threadfence();                   // reader-side acquire
      }
      __syncthreads();
    }
  }
  __syncthreads();

  // write rnn*fin as bf16 hi/lo A operand (block-local data only)
  for (int i = tid; i < 8192; i += 128) {
    int t = i >> 7, r = i & 127, vl2 = r >> 5, bb = r & 31;
    int row = (bb << 6) + t;
    int col = (bid << 2) + vl2;
    float rv = rnn_s[i] * g_fin[row*512 + col];
    split_bf16(rv, &g_Ah[row*512 + col], &g_Al[row*512 + col]);
  }
}

// ---------------- HMMA (mma.sync) bf16x3 GEMM ----------------
// C[2048, Ntot] = (Ah+Al)[2048,512] @ (Bh+Bl)[Ntot,512]^T + bias
// CTA tile 128x128, 8 warps (2M x 4N), warp tile 64x32, BK=32, cp.async 2-stage.
// zt_mode: scatter epilogue into g_zt gate-packed layout instead of C.

__device__ __forceinline__ uint32_t smem_u32(const void* p) {
  uint32_t a;
  asm("{ .reg .u64 t; cvta.to.shared.u64 t, %1; cvt.u32.u64 %0, t; }" : "=r"(a) : "l"(p));
  return a;
}
__device__ __forceinline__ void cp16(uint32_t dst, const void* src) {
  asm volatile("cp.async.cg.shared.global [%0], [%1], 16;" :: "r"(dst), "l"(src));
}
#define LDSM4(d, a) asm volatile( \
  "ldmatrix.sync.aligned.m8n8.x4.shared.b16 {%0,%1,%2,%3}, [%4];" \
  : "=r"((d)[0]), "=r"((d)[1]), "=r"((d)[2]), "=r"((d)[3]) : "r"(a))
#define LDSM2(d, a) asm volatile( \
  "ldmatrix.sync.aligned.m8n8.x2.shared.b16 {%0,%1}, [%2];" \
  : "=r"((d)[0]), "=r"((d)[1]) : "r"(a))
#define MMA16816(ac, af, bf) asm volatile( \
  "mma.sync.aligned.m16n8k16.row.col.f32.bf16.bf16.f32 " \
  "{%0,%1,%2,%3}, {%4,%5,%6,%7}, {%8,%9}, {%0,%1,%2,%3};" \
  : "+f"((ac)[0]), "+f"((ac)[1]), "+f"((ac)[2]), "+f"((ac)[3]) \
  : "r"((af)[0]), "r"((af)[1]), "r"((af)[2]), "r"((af)[3]), \
    "r"((bf)[0]), "r"((bf)[1]))

#define TPB 10240
#define STG 40960
#define OFF_AH 0
#define OFF_AL TPB
#define OFF_BH (2*TPB)
#define OFF_BL (3*TPB)
#define GEMM_SMEM (2*STG)

__global__ __launch_bounds__(256, 2) void gemm_mma_kernel(
    const __nv_bfloat16* __restrict__ Ah, const __nv_bfloat16* __restrict__ Al,
    const __nv_bfloat16* __restrict__ Bh, const __nv_bfloat16* __restrict__ Bl,
    const float* __restrict__ bias, float* __restrict__ C, int Ntot, int zt_mode)
{
  extern __shared__ char smem[];
  uint32_t sb = smem_u32(smem);
  int tid = threadIdx.x, wid = tid >> 5, lane = tid & 31;
  int wm = wid >> 2, wn = wid & 3;
  int M0 = blockIdx.y << 7, N0 = blockIdx.x << 7;

  int r0 = tid >> 2, c0 = (tid & 3);
  uint32_t ld_d0 = (uint32_t)r0 * 80u + (uint32_t)c0 * 16u;
  uint32_t ld_d1 = (uint32_t)(r0 + 64) * 80u + (uint32_t)c0 * 16u;

  uint32_t aBase = (uint32_t)((wm << 6) + (lane & 7) + (((lane >> 3) & 1) << 3)) * 80u
                 + (uint32_t)((lane >> 4) << 4);
  uint32_t bBase = (uint32_t)(((wn << 5) + (lane & 7))) * 80u
                 + (uint32_t)(((lane >> 3) & 1) << 4);

  float acc[4][4][4];
#pragma unroll
  for (int i = 0; i < 4; i++)
#pragma unroll
    for (int j = 0; j < 4; j++)
#pragma unroll
      for (int q = 0; q < 4; q++) acc[i][j][q] = 0.f;

  {
    uint32_t s0 = sb;
    size_t gA0 = (size_t)(M0 + r0) * 512 + c0 * 8;
    size_t gA1 = (size_t)(M0 + r0 + 64) * 512 + c0 * 8;
    size_t gB0 = (size_t)(N0 + r0) * 512 + c0 * 8;
    size_t gB1 = (size_t)(N0 + r0 + 64) * 512 + c0 * 8;
    cp16(s0 + OFF_AH + ld_d0, Ah + gA0); cp16(s0 + OFF_AH + ld_d1, Ah + gA1);
    cp16(s0 + OFF_AL + ld_d0, Al + gA0); cp16(s0 + OFF_AL + ld_d1, Al + gA1);
    cp16(s0 + OFF_BH + ld_d0, Bh + gB0); cp16(s0 + OFF_BH + ld_d1, Bh + gB1);
    cp16(s0 + OFF_BL + ld_d0, Bl + gB0); cp16(s0 + OFF_BL + ld_d1, Bl + gB1);
    asm volatile("cp.async.commit_group;" ::: "memory");
  }

  for (int kc = 0; kc < 16; kc++) {
    asm volatile("cp.async.wait_group 0;" ::: "memory");
    __syncthreads();
    if (kc + 1 < 16) {
      uint32_t s1 = sb + ((kc + 1) & 1) * STG;
      int kk = (kc + 1) * 32;
      size_t gA0 = (size_t)(M0 + r0) * 512 + kk + c0 * 8;
      size_t gA1 = (size_t)(M0 + r0 + 64) * 512 + kk + c0 * 8;
      size_t gB0 = (size_t)(N0 + r0) * 512 + kk + c0 * 8;
      size_t gB1 = (size_t)(N0 + r0 + 64) * 512 + kk + c0 * 8;
      cp16(s1 + OFF_AH + ld_d0, Ah + gA0); cp16(s1 + OFF_AH + ld_d1, Ah + gA1);
      cp16(s1 + OFF_AL + ld_d0, Al + gA0); cp16(s1 + OFF_AL + ld_d1, Al + gA1);
      cp16(s1 + OFF_BH + ld_d0, Bh + gB0); cp16(s1 + OFF_BH + ld_d1, Bh + gB1);
      cp16(s1 + OFF_BL + ld_d0, Bl + gB0); cp16(s1 + OFF_BL + ld_d1, Bl + gB1);
      asm volatile("cp.async.commit_group;" ::: "memory");
    }

    uint32_t s0 = sb + (kc & 1) * STG;
#pragma unroll
    for (int ks = 0; ks < 2; ks++) {
      uint32_t bh[4][2], bl[4][2];
#pragma unroll
      for (int nt = 0; nt < 4; nt++) {
        uint32_t bo = bBase + (uint32_t)(nt * 640 + ks * 32);
        LDSM2(bh[nt], s0 + OFF_BH + bo);
        LDSM2(bl[nt], s0 + OFF_BL + bo);
      }
#pragma unroll
      for (int mt = 0; mt < 4; mt++) {
        uint32_t ah[4], al[4];
        uint32_t ao = aBase + (uint32_t)(mt * 1280 + ks * 32);
        LDSM4(ah, s0 + OFF_AH + ao);
        LDSM4(al, s0 + OFF_AL + ao);
#pragma unroll
        for (int nt = 0; nt < 4; nt++) MMA16816(acc[mt][nt], ah, bh[nt]);
#pragma unroll
        for (int nt = 0; nt < 4; nt++) MMA16816(acc[mt][nt], ah, bl[nt]);
#pragma unroll
        for (int nt = 0; nt < 4; nt++) MMA16816(acc[mt][nt], al, bh[nt]);
      }
    }
    __syncthreads();
  }

  // epilogue
  if (!zt_mode) {
#pragma unroll
    for (int mt = 0; mt < 4; mt++) {
      int grow = M0 + (wm << 6) + mt * 16 + (lane >> 2);
#pragma unroll
      for (int nt = 0; nt < 4; nt++) {
        int gcol = N0 + (wn << 5) + nt * 8 + (lane & 3) * 2;
        float bx = __ldg(&bias[gcol]), by = __ldg(&bias[gcol + 1]);
        float2 o0 = make_float2(acc[mt][nt][0] + bx, acc[mt][nt][1] + by);
        float2 o1 = make_float2(acc[mt][nt][2] + bx, acc[mt][nt][3] + by);
        *(float2*)&C[(size_t)grow * Ntot + gcol] = o0;
        *(float2*)&C[(size_t)(grow + 8) * Ntot + gcol] = o1;
      }
    }
  } else {
    // scatter into g_zt[((t*512+v)*32+b)*4 + g]; row=(b*64+t), col=(g*512+v)
#pragma unroll
    for (int mt = 0; mt < 4; mt++) {
      int grow0 = M0 + (wm << 6) + mt * 16 + (lane >> 2);
#pragma unroll
      for (int nt = 0; nt < 4; nt++) {
        int gcol0 = N0 + (wn << 5) + nt * 8 + (lane & 3) * 2;
#pragma unroll
        for (int q = 0; q < 4; q++) {
          int grow = grow0 + ((q >> 1) << 3);       // +0 or +8
          int gcol = gcol0 + (q & 1);
          int b = grow >> 6, t = grow & 63;
          int g = gcol >> 9, v = gcol & 511;
          g_zt[(((t << 9) + v) * 32 + b) * 4 + g] = acc[mt][nt][q] + __ldg(&bias[gcol]);
        }
      }
    }
  }
}

// ---------------- host ----------------
extern "C" void kernel_launch(void* const* d_in, const int* in_sizes, int n_in,
                              void* d_out, int out_size) {
  (void)in_sizes; (void)n_in; (void)out_size;
  const float* images_emb = (const float*)d_in[1];
  const void*  targets    = d_in[2];
  const float* emb_table  = (const float*)d_in[3];
  const float* W_in       = (const float*)d_in[4];
  const float* W_rec      = (const float*)d_in[5];
  const float* b_lstm     = (const float*)d_in[6];
  const float* W_out      = (const float*)d_in[7];
  const float* b_out      = (const float*)d_in[8];
  float* out = (float*)d_out;

  void *pah = nullptr, *pal = nullptr, *pbth = nullptr, *pbtl = nullptr,
       *pwth = nullptr, *pwtl = nullptr;
  cudaGetSymbolAddress(&pah,  g_Ah);
  cudaGetSymbolAddress(&pal,  g_Al);
  cudaGetSymbolAddress(&pbth, g_Bth);
  cudaGetSymbolAddress(&pbtl, g_Btl);
  cudaGetSymbolAddress(&pwth, g_Wth);
  cudaGetSymbolAddress(&pwtl, g_Wtl);

  cudaFuncSetAttribute(gemm_mma_kernel,
                       cudaFuncAttributeMaxDynamicSharedMemorySize, GEMM_SMEM);
  cudaFuncSetAttribute(lstm_persist_kernel,
                       cudaFuncAttributeMaxDynamicSharedMemorySize, 65536);

  uint32_t k1a, k1b, k2a, k2b, k3a, k3b;
  tf2x32(0u, 42u, 0u, 0u, &k1a, &k1b);
  tf2x32(0u, 42u, 0u, 1u, &k2a, &k2b);
  tf2x32(0u, 42u, 0u, 2u, &k3a, &k3b);

  detect_kernel<<<1, 128>>>((const int*)targets);
  masks_kernel<<<4096, 256>>>(k1a, k1b, k2a, k2b, k3a, k3b, W_rec);
  embed_kernel<<<4096, 256>>>(images_emb, targets, emb_table);

  transpose_split_kernel<<<dim3(64, 16),   dim3(32, 8)>>>(W_in,  (__nv_bfloat16*)pwth, (__nv_bfloat16*)pwtl, 2048);
  transpose_split_kernel<<<dim3(1000, 16), dim3(32, 8)>>>(W_out, (__nv_bfloat16*)pbth, (__nv_bfloat16*)pbtl, V_);

  // z_in = x @ W_in + b_lstm, scattered straight into gate-packed g_zt
  gemm_mma_kernel<<<dim3(16, 16), 256, GEMM_SMEM>>>(
      (const __nv_bfloat16*)pah, (const __nv_bfloat16*)pal,
      (const __nv_bfloat16*)pwth, (const __nv_bfloat16*)pwtl,
      b_lstm, nullptr, 2048, 1);

  // all 64 recurrence steps in one persistent kernel
  lstm_persist_kernel<<<128, 128, 65536>>>();

  // predictions = rnn_out @ W_out + b_out   [2048, 32000]
  gemm_mma_kernel<<<dim3(250, 16), 256, GEMM_SMEM>>>(
      (const __nv_bfloat16*)pah, (const __nv_bfloat16*)pal,
      (const __nv_bfloat16*)pbth, (const __nv_bfloat16*)pbtl,
      b_out, out, V_, 0);
}

// round 12
// speedup vs baseline: 1.9576x; 1.9576x over previous
#include <cuda_runtime.h>
#include <cuda_bf16.h>
#include <cstdint>
#include <math.h>

// Problem dims
#define B_ 32
#define L_ 64
#define E_ 512
#define U_ 512
#define V_ 32000
#define KEEPP 0.7f

// ---------------- static device scratch (no runtime allocation) ----------------
__device__ float  g_word_mask[B_*E_];          // [b][e]
__device__ float4 g_rm4[U_*B_];                // [u][b] -> 4 gate masks
__device__ float  g_fin[B_*L_*U_];             // [b*64+t][u]
__device__ float4 g_Wr4[U_*U_];                // [u][v] -> {W[u][g*512+v]}_g
__device__ float4 g_hmA[U_*B_];                // masked h ping
__device__ float4 g_hmB[U_*B_];                // masked h pong
__device__ float  g_c[U_*B_];                  // cell state [v*32+b]
__device__ float  g_zin[B_*L_*4*U_];           // x@W_in + b, rows = b*64+t
__device__ int    g_is64;

// bf16 split operands for tensor-core GEMMs
__device__ __nv_bfloat16 g_Bth[(size_t)V_*512];   // W_out^T hi  [32000,512]
__device__ __nv_bfloat16 g_Btl[(size_t)V_*512];   // W_out^T lo
__device__ __nv_bfloat16 g_Wth[2048*512];         // W_in^T hi   [2048,512]
__device__ __nv_bfloat16 g_Wtl[2048*512];         // W_in^T lo
__device__ __nv_bfloat16 g_Ah[2048*512];          // A hi (x, later rnn)
__device__ __nv_bfloat16 g_Al[2048*512];          // A lo

// ---------------- threefry2x32, matches JAX exactly ----------------
__host__ __device__ __forceinline__ void tf2x32(uint32_t k0, uint32_t k1,
                                                uint32_t x0, uint32_t x1,
                                                uint32_t* o0, uint32_t* o1) {
  uint32_t ks2 = 0x1BD11BDAu ^ k0 ^ k1;
  uint32_t v0 = x0 + k0, v1 = x1 + k1;
#define TFR(r) { v0 += v1; v1 = (v1 << (r)) | (v1 >> (32 - (r))); v1 ^= v0; }
  TFR(13) TFR(15) TFR(26) TFR(6)  v0 += k1;  v1 += ks2 + 1u;
  TFR(17) TFR(29) TFR(16) TFR(24) v0 += ks2; v1 += k0 + 2u;
  TFR(13) TFR(15) TFR(26) TFR(6)  v0 += k0;  v1 += k1 + 3u;
  TFR(17) TFR(29) TFR(16) TFR(24) v0 += k1;  v1 += ks2 + 4u;
  TFR(13) TFR(15) TFR(26) TFR(6)  v0 += ks2; v1 += k0 + 5u;
#undef TFR
  *o0 = v0; *o1 = v1;
}

__device__ __forceinline__ float bern_val(uint32_t ka, uint32_t kb, uint32_t idx) {
  uint32_t a, b;
  tf2x32(ka, kb, 0u, idx, &a, &b);
  uint32_t bits = a ^ b;
  float u = __uint_as_float((bits >> 9) | 0x3f800000u) - 1.0f;
  return (u < KEEPP) ? (1.0f / KEEPP) : 0.0f;
}

__device__ __forceinline__ void split_bf16(float v, __nv_bfloat16* h, __nv_bfloat16* l) {
  __nv_bfloat16 hh = __float2bfloat16(v);
  *h = hh;
  *l = __float2bfloat16(v - __bfloat162float(hh));
}

// ---------------- small kernels ----------------
__global__ void detect_kernel(const int* __restrict__ tw) {
  __shared__ int s;
  if (threadIdx.x == 0) s = 0;
  __syncthreads();
  int any = 0;
  for (int i = threadIdx.x; i < 1024; i += blockDim.x) any |= tw[2*i + 1];
  if (any) atomicOr(&s, 1);
  __syncthreads();
  if (threadIdx.x == 0) g_is64 = (s == 0) ? 1 : 0;
}

// masks + W_rec repack + h0/cell init, all fused
__global__ void masks_kernel(uint32_t k1a, uint32_t k1b, uint32_t k2a, uint32_t k2b,
                             uint32_t k3a, uint32_t k3b,
                             const float* __restrict__ W_rec) {
  uint32_t idx = blockIdx.x * blockDim.x + threadIdx.x;   // exactly 1048576 threads
  if (idx < (uint32_t)(B_*E_)) g_word_mask[idx] = bern_val(k1a, k1b, idx);
  if (idx < (uint32_t)(4*B_*U_)) {
    uint32_t g = idx >> 14, b = (idx >> 9) & 31u, u = idx & 511u;
    ((float*)g_rm4)[(u*32u + b)*4u + g] = bern_val(k2a, k2b, idx);
  }
  if (idx < (uint32_t)(U_*B_)) {
    g_hmA[idx] = make_float4(0.f, 0.f, 0.f, 0.f);
    g_c[idx] = 0.f;
  }
  if (idx < 262144u) {
    int v = idx & 511, u = idx >> 9;
    const float* r = W_rec + (size_t)u * 2048 + v;
    g_Wr4[u*512 + v] = make_float4(r[0], r[512], r[1024], r[1536]);
  }
  g_fin[idx] = bern_val(k3a, k3b, idx);
}

// embedding + word dropout -> bf16 hi/lo A operand directly
__global__ void embed_kernel(const float* __restrict__ images_emb,
                             const void* __restrict__ targets,
                             const float* __restrict__ emb_table) {
  int idx = blockIdx.x * blockDim.x + threadIdx.x;        // 1048576
  int e = idx & 511, t = (idx >> 9) & 63, b = idx >> 15;
  float v;
  if (t == 0) {
    v = images_emb[b*E_ + e];
  } else {
    int w;
    if (g_is64) w = (int)((const long long*)targets)[b*L_ + (t-1)];
    else        w = ((const int*)targets)[b*L_ + (t-1)];
    v = emb_table[(size_t)w * E_ + e] * g_word_mask[b*E_ + e];
  }
  split_bf16(v, &g_Ah[idx], &g_Al[idx]);
}

// transpose [512, N] fp32 -> [N, 512] bf16 hi/lo
__global__ void transpose_split_kernel(const float* __restrict__ in,
                                       __nv_bfloat16* __restrict__ oh,
                                       __nv_bfloat16* __restrict__ ol, int N) {
  __shared__ float tile[32][33];
  int tx = threadIdx.x, ty = threadIdx.y;
  int n0 = blockIdx.x * 32, k0 = blockIdx.y * 32;
#pragma unroll
  for (int j = ty; j < 32; j += 8)
    tile[j][tx] = in[(size_t)(k0 + j) * N + n0 + tx];
  __syncthreads();
#pragma unroll
  for (int j = ty; j < 32; j += 8) {
    float v = tile[tx][j];
    size_t o = (size_t)(n0 + j) * 512 + k0 + tx;
    split_bf16(v, &oh[o], &ol[o]);
  }
}

// ---------------- LSTM step (one launch per timestep) ----------------
// 64 blocks x 256 threads; block owns v in [8*bid, 8*bid+8); thread = (vl, b).
// W slice in dynamic smem (64KB); per-launch L1 flush gives cross-block coherence.
__global__ __launch_bounds__(256) void lstm_step_kernel(int t, int pp) {
  extern __shared__ float4 ws4[];            // [u][vl] : 4096 float4 = 64KB
  const float4* __restrict__ hin  = pp ? g_hmB : g_hmA;
  float4* __restrict__       hout = pp ? g_hmA : g_hmB;

  int tid = threadIdx.x, b = tid & 31, vl = tid >> 5;
  int v = (blockIdx.x << 3) + vl;

  for (int i = tid; i < 4096; i += 256) {
    int u = i >> 3, w = i & 7;
    ws4[i] = g_Wr4[u*512 + (blockIdx.x << 3) + w];
  }
  __syncthreads();

  float ax = 0.f, ay = 0.f, az = 0.f, aw = 0.f;
  const float4* hp = hin + b;
  const float4* wp = ws4 + vl;
#pragma unroll 8
  for (int u = 0; u < 512; u++) {
    float4 h4 = hp[u*32];
    float4 w4 = wp[u*8];
    ax = fmaf(h4.x, w4.x, ax);
    ay = fmaf(h4.y, w4.y, ay);
    az = fmaf(h4.z, w4.z, az);
    aw = fmaf(h4.w, w4.w, aw);
  }

  int row = (b << 6) + t;
  const float* zr = g_zin + (size_t)row * 2048 + v;
  float zi = zr[0]    + ax;
  float zf = zr[512]  + ay;
  float zg = zr[1024] + az;
  float zo = zr[1536] + aw;

  float ig = 1.f / (1.f + expf(-zi));
  float fg = 1.f / (1.f + expf(-zf));
  float gv = tanhf(zg);
  float og = 1.f / (1.f + expf(-zo));

  int ci = v*32 + b;
  float cn = fmaf(fg, g_c[ci], ig * gv);
  g_c[ci] = cn;
  float hn = og * tanhf(cn);

  int ro = row*512 + v;
  float rv = hn * g_fin[ro];
  split_bf16(rv, &g_Ah[ro], &g_Al[ro]);

  float4 m = g_rm4[ci];
  hout[ci] = make_float4(hn*m.x, hn*m.y, hn*m.z, hn*m.w);
}

// ---------------- HMMA (mma.sync) bf16x3 GEMM, 4-stage cp.async ----------------
// C[2048, Ntot] = (Ah+Al)[2048,512] @ (Bh+Bl)[Ntot,512]^T + bias
// CTA tile 128x128, 8 warps (2M x 4N), warp tile 64x32, BK=32.

__device__ __forceinline__ uint32_t smem_u32(const void* p) {
  uint32_t a;
  asm("{ .reg .u64 t; cvta.to.shared.u64 t, %1; cvt.u32.u64 %0, t; }" : "=r"(a) : "l"(p));
  return a;
}
__device__ __forceinline__ void cp16(uint32_t dst, const void* src) {
  asm volatile("cp.async.cg.shared.global [%0], [%1], 16;" :: "r"(dst), "l"(src));
}
#define LDSM4(d, a) asm volatile( \
  "ldmatrix.sync.aligned.m8n8.x4.shared.b16 {%0,%1,%2,%3}, [%4];" \
  : "=r"((d)[0]), "=r"((d)[1]), "=r"((d)[2]), "=r"((d)[3]) : "r"(a))
#define LDSM2(d, a) asm volatile( \
  "ldmatrix.sync.aligned.m8n8.x2.shared.b16 {%0,%1}, [%2];" \
  : "=r"((d)[0]), "=r"((d)[1]) : "r"(a))
#define MMA16816(ac, af, bf) asm volatile( \
  "mma.sync.aligned.m16n8k16.row.col.f32.bf16.bf16.f32 " \
  "{%0,%1,%2,%3}, {%4,%5,%6,%7}, {%8,%9}, {%0,%1,%2,%3};" \
  : "+f"((ac)[0]), "+f"((ac)[1]), "+f"((ac)[2]), "+f"((ac)[3]) \
  : "r"((af)[0]), "r"((af)[1]), "r"((af)[2]), "r"((af)[3]), \
    "r"((bf)[0]), "r"((bf)[1]))

#define TPB 10240
#define STG 40960
#define OFF_AH 0
#define OFF_AL TPB
#define OFF_BH (2*TPB)
#define OFF_BL (3*TPB)
#define GEMM_SMEM (4*STG)   // 4 stages = 160KB

__global__ __launch_bounds__(256) void gemm_mma_kernel(
    const __nv_bfloat16* __restrict__ Ah, const __nv_bfloat16* __restrict__ Al,
    const __nv_bfloat16* __restrict__ Bh, const __nv_bfloat16* __restrict__ Bl,
    const float* __restrict__ bias, float* __restrict__ C, int Ntot)
{
  extern __shared__ char smem[];
  uint32_t sb = smem_u32(smem);
  int tid = threadIdx.x, wid = tid >> 5, lane = tid & 31;
  int wm = wid >> 2, wn = wid & 3;
  int M0 = blockIdx.y << 7, N0 = blockIdx.x << 7;

  int r0 = tid >> 2, c0 = (tid & 3);
  uint32_t ld_d0 = (uint32_t)r0 * 80u + (uint32_t)c0 * 16u;
  uint32_t ld_d1 = (uint32_t)(r0 + 64) * 80u + (uint32_t)c0 * 16u;

  uint32_t aBase = (uint32_t)((wm << 6) + (lane & 7) + (((lane >> 3) & 1) << 3)) * 80u
                 + (uint32_t)((lane >> 4) << 4);
  uint32_t bBase = (uint32_t)(((wn << 5) + (lane & 7))) * 80u
                 + (uint32_t)(((lane >> 3) & 1) << 4);

  float acc[4][4][4];
#pragma unroll
  for (int i = 0; i < 4; i++)
#pragma unroll
    for (int j = 0; j < 4; j++)
#pragma unroll
      for (int q = 0; q < 4; q++) acc[i][j][q] = 0.f;

  // prologue: prefetch stages 0..2 (kc = 0..2)
#pragma unroll
  for (int ps = 0; ps < 3; ps++) {
    uint32_t s1 = sb + (uint32_t)ps * STG;
    int kk = ps * 32;
    size_t gA0 = (size_t)(M0 + r0) * 512 + kk + c0 * 8;
    size_t gA1 = (size_t)(M0 + r0 + 64) * 512 + kk + c0 * 8;
    size_t gB0 = (size_t)(N0 + r0) * 512 + kk + c0 * 8;
    size_t gB1 = (size_t)(N0 + r0 + 64) * 512 + kk + c0 * 8;
    cp16(s1 + OFF_AH + ld_d0, Ah + gA0); cp16(s1 + OFF_AH + ld_d1, Ah + gA1);
    cp16(s1 + OFF_AL + ld_d0, Al + gA0); cp16(s1 + OFF_AL + ld_d1, Al + gA1);
    cp16(s1 + OFF_BH + ld_d0, Bh + gB0); cp16(s1 + OFF_BH + ld_d1, Bh + gB1);
    cp16(s1 + OFF_BL + ld_d0, Bl + gB0); cp16(s1 + OFF_BL + ld_d1, Bl + gB1);
    asm volatile("cp.async.commit_group;" ::: "memory");
  }

  for (int kc = 0; kc < 16; kc++) {
    asm volatile("cp.async.wait_group 2;" ::: "memory");
    __syncthreads();
    // refill stage (kc+3)%4 — its previous contents were consumed at kc-1,
    // and the sync above makes that globally visible.
    if (kc + 3 < 16) {
      uint32_t s1 = sb + (uint32_t)((kc + 3) & 3) * STG;
      int kk = (kc + 3) * 32;
      size_t gA0 = (size_t)(M0 + r0) * 512 + kk + c0 * 8;
      size_t gA1 = (size_t)(M0 + r0 + 64) * 512 + kk + c0 * 8;
      size_t gB0 = (size_t)(N0 + r0) * 512 + kk + c0 * 8;
      size_t gB1 = (size_t)(N0 + r0 + 64) * 512 + kk + c0 * 8;
      cp16(s1 + OFF_AH + ld_d0, Ah + gA0); cp16(s1 + OFF_AH + ld_d1, Ah + gA1);
      cp16(s1 + OFF_AL + ld_d0, Al + gA0); cp16(s1 + OFF_AL + ld_d1, Al + gA1);
      cp16(s1 + OFF_BH + ld_d0, Bh + gB0); cp16(s1 + OFF_BH + ld_d1, Bh + gB1);
      cp16(s1 + OFF_BL + ld_d0, Bl + gB0); cp16(s1 + OFF_BL + ld_d1, Bl + gB1);
      asm volatile("cp.async.commit_group;" ::: "memory");
    } else {
      asm volatile("cp.async.commit_group;" ::: "memory");  // keep group count in step
    }

    uint32_t s0 = sb + (uint32_t)(kc & 3) * STG;
#pragma unroll
    for (int ks = 0; ks < 2; ks++) {
      uint32_t bh[4][2], bl[4][2];
#pragma unroll
      for (int nt = 0; nt < 4; nt++) {
        uint32_t bo = bBase + (uint32_t)(nt * 640 + ks * 32);
        LDSM2(bh[nt], s0 + OFF_BH + bo);
        LDSM2(bl[nt], s0 + OFF_BL + bo);
      }
#pragma unroll
      for (int mt = 0; mt < 4; mt++) {
        uint32_t ah[4], al[4];
        uint32_t ao = aBase + (uint32_t)(mt * 1280 + ks * 32);
        LDSM4(ah, s0 + OFF_AH + ao);
        LDSM4(al, s0 + OFF_AL + ao);
#pragma unroll
        for (int nt = 0; nt < 4; nt++) MMA16816(acc[mt][nt], ah, bh[nt]);
#pragma unroll
        for (int nt = 0; nt < 4; nt++) MMA16816(acc[mt][nt], ah, bl[nt]);
#pragma unroll
        for (int nt = 0; nt < 4; nt++) MMA16816(acc[mt][nt], al, bh[nt]);
      }
    }
    __syncthreads();
  }

  // epilogue
#pragma unroll
  for (int mt = 0; mt < 4; mt++) {
    int grow = M0 + (wm << 6) + mt * 16 + (lane >> 2);
#pragma unroll
    for (int nt = 0; nt < 4; nt++) {
      int gcol = N0 + (wn << 5) + nt * 8 + (lane & 3) * 2;
      float bx = __ldg(&bias[gcol]), by = __ldg(&bias[gcol + 1]);
      float2 o0 = make_float2(acc[mt][nt][0] + bx, acc[mt][nt][1] + by);
      float2 o1 = make_float2(acc[mt][nt][2] + bx, acc[mt][nt][3] + by);
      *(float2*)&C[(size_t)grow * Ntot + gcol] = o0;
      *(float2*)&C[(size_t)(grow + 8) * Ntot + gcol] = o1;
    }
  }
}

// ---------------- host ----------------
extern "C" void kernel_launch(void* const* d_in, const int* in_sizes, int n_in,
                              void* d_out, int out_size) {
  (void)in_sizes; (void)n_in; (void)out_size;
  const float* images_emb = (const float*)d_in[1];
  const void*  targets    = d_in[2];
  const float* emb_table  = (const float*)d_in[3];
  const float* W_in       = (const float*)d_in[4];
  const float* W_rec      = (const float*)d_in[5];
  const float* b_lstm     = (const float*)d_in[6];
  const float* W_out      = (const float*)d_in[7];
  const float* b_out      = (const float*)d_in[8];
  float* out = (float*)d_out;

  void *pzin = nullptr, *pah = nullptr, *pal = nullptr, *pbth = nullptr,
       *pbtl = nullptr, *pwth = nullptr, *pwtl = nullptr;
  cudaGetSymbolAddress(&pzin, g_zin);
  cudaGetSymbolAddress(&pah,  g_Ah);
  cudaGetSymbolAddress(&pal,  g_Al);
  cudaGetSymbolAddress(&pbth, g_Bth);
  cudaGetSymbolAddress(&pbtl, g_Btl);
  cudaGetSymbolAddress(&pwth, g_Wth);
  cudaGetSymbolAddress(&pwtl, g_Wtl);

  cudaFuncSetAttribute(gemm_mma_kernel,
                       cudaFuncAttributeMaxDynamicSharedMemorySize, GEMM_SMEM);
  cudaFuncSetAttribute(lstm_step_kernel,
                       cudaFuncAttributeMaxDynamicSharedMemorySize, 65536);

  uint32_t k1a, k1b, k2a, k2b, k3a, k3b;
  tf2x32(0u, 42u, 0u, 0u, &k1a, &k1b);
  tf2x32(0u, 42u, 0u, 1u, &k2a, &k2b);
  tf2x32(0u, 42u, 0u, 2u, &k3a, &k3b);

  detect_kernel<<<1, 128>>>((const int*)targets);
  masks_kernel<<<4096, 256>>>(k1a, k1b, k2a, k2b, k3a, k3b, W_rec);
  embed_kernel<<<4096, 256>>>(images_emb, targets, emb_table);

  transpose_split_kernel<<<dim3(64, 16),   dim3(32, 8)>>>(W_in,  (__nv_bfloat16*)pwth, (__nv_bfloat16*)pwtl, 2048);
  transpose_split_kernel<<<dim3(1000, 16), dim3(32, 8)>>>(W_out, (__nv_bfloat16*)pbth, (__nv_bfloat16*)pbtl, V_);

  // z_in = x @ W_in + b_lstm   [2048, 2048]
  gemm_mma_kernel<<<dim3(16, 16), 256, GEMM_SMEM>>>(
      (const __nv_bfloat16*)pah, (const __nv_bfloat16*)pal,
      (const __nv_bfloat16*)pwth, (const __nv_bfloat16*)pwtl,
      b_lstm, (float*)pzin, 2048);

  // recurrence: 64 per-step launches (graph-captured)
  for (int t = 0; t < 64; t++)
    lstm_step_kernel<<<64, 256, 65536>>>(t, t & 1);

  // predictions = rnn_out @ W_out + b_out   [2048, 32000]
  gemm_mma_kernel<<<dim3(250, 16), 256, GEMM_SMEM>>>(
      (const __nv_bfloat16*)pah, (const __nv_bfloat16*)pal,
      (const __nv_bfloat16*)pbth, (const __nv_bfloat16*)pbtl,
      b_out, out, V_);
}

// round 16
// speedup vs baseline: 4.6296x; 2.3650x over previous
#include <cuda_runtime.h>
#include <cuda_bf16.h>
#include <cstdint>
#include <math.h>

// Problem dims
#define B_ 32
#define L_ 64
#define E_ 512
#define U_ 512
#define V_ 32000
#define KEEPP 0.7f

// ---------------- static device scratch (no runtime allocation) ----------------
__device__ float4 g_rm4[U_*B_];                // [u][b] -> 4 gate masks
__device__ float  g_fin[B_*L_*U_];             // [b*64+t][u]
__device__ float4 g_Wr4[U_*U_];                // [u][v] -> {W[u][g*512+v]}_g
__device__ float4 g_hmA[U_*B_];                // masked h ping
__device__ float4 g_hmB[U_*B_];                // masked h pong
__device__ float  g_c[U_*B_];                  // cell state [v*32+b]
__device__ float  g_zin[B_*L_*4*U_];           // x@W_in + b, rows = b*64+t
__device__ int    g_is64;

// bf16 split operands for tensor-core GEMMs
__device__ __nv_bfloat16 g_Bth[(size_t)V_*512];   // W_out^T hi  [32000,512]
__device__ __nv_bfloat16 g_Btl[(size_t)V_*512];   // W_out^T lo
__device__ __nv_bfloat16 g_Wth[2048*512];         // W_in^T hi   [2048,512]
__device__ __nv_bfloat16 g_Wtl[2048*512];         // W_in^T lo
__device__ __nv_bfloat16 g_Ah[2048*512];          // A hi (x, later rnn)
__device__ __nv_bfloat16 g_Al[2048*512];          // A lo

// ---------------- threefry2x32, matches JAX exactly ----------------
__host__ __device__ __forceinline__ void tf2x32(uint32_t k0, uint32_t k1,
                                                uint32_t x0, uint32_t x1,
                                                uint32_t* o0, uint32_t* o1) {
  uint32_t ks2 = 0x1BD11BDAu ^ k0 ^ k1;
  uint32_t v0 = x0 + k0, v1 = x1 + k1;
#define TFR(r) { v0 += v1; v1 = (v1 << (r)) | (v1 >> (32 - (r))); v1 ^= v0; }
  TFR(13) TFR(15) TFR(26) TFR(6)  v0 += k1;  v1 += ks2 + 1u;
  TFR(17) TFR(29) TFR(16) TFR(24) v0 += ks2; v1 += k0 + 2u;
  TFR(13) TFR(15) TFR(26) TFR(6)  v0 += k0;  v1 += k1 + 3u;
  TFR(17) TFR(29) TFR(16) TFR(24) v0 += k1;  v1 += ks2 + 4u;
  TFR(13) TFR(15) TFR(26) TFR(6)  v0 += ks2; v1 += k0 + 5u;
#undef TFR
  *o0 = v0; *o1 = v1;
}

__device__ __forceinline__ float bern_val(uint32_t ka, uint32_t kb, uint32_t idx) {
  uint32_t a, b;
  tf2x32(ka, kb, 0u, idx, &a, &b);
  uint32_t bits = a ^ b;
  float u = __uint_as_float((bits >> 9) | 0x3f800000u) - 1.0f;
  return (u < KEEPP) ? (1.0f / KEEPP) : 0.0f;
}

__device__ __forceinline__ void split_bf16(float v, __nv_bfloat16* h, __nv_bfloat16* l) {
  __nv_bfloat16 hh = __float2bfloat16(v);
  *h = hh;
  *l = __float2bfloat16(v - __bfloat162float(hh));
}

// ---------------- fused masks + W_rec repack + state init + dtype detect ----------------
__global__ void masks_kernel(uint32_t k2a, uint32_t k2b, uint32_t k3a, uint32_t k3b,
                             const float* __restrict__ W_rec,
                             const int* __restrict__ tgt_words) {
  uint32_t idx = blockIdx.x * blockDim.x + threadIdx.x;   // exactly 1048576 threads
  if (blockIdx.x == 0) {
    int any = 0;
    for (int i = threadIdx.x; i < 1024; i += 256) any |= tgt_words[2*i + 1];
    any = __syncthreads_or(any);
    if (threadIdx.x == 0) g_is64 = any ? 0 : 1;
  }
  if (idx < (uint32_t)(4*B_*U_)) {
    uint32_t g = idx >> 14, b = (idx >> 9) & 31u, u = idx & 511u;
    ((float*)g_rm4)[(u*32u + b)*4u + g] = bern_val(k2a, k2b, idx);
  }
  if (idx < (uint32_t)(U_*B_)) {
    g_hmA[idx] = make_float4(0.f, 0.f, 0.f, 0.f);
    g_c[idx] = 0.f;
  }
  if (idx < 262144u) {
    int v = idx & 511, u = idx >> 9;
    const float* r = W_rec + (size_t)u * 2048 + v;
    g_Wr4[u*512 + v] = make_float4(r[0], r[512], r[1024], r[1536]);
  }
  g_fin[idx] = bern_val(k3a, k3b, idx);
}

// combined transpose: [512,N] fp32 -> [N,512] bf16 hi/lo for W_in and W_out
__global__ void transpose_split_kernel(const float* __restrict__ Win,
                                       const float* __restrict__ Wout) {
  __shared__ float tile[32][33];
  int bx = blockIdx.x;
  const float* in; __nv_bfloat16 *oh, *ol; int N, n0;
  if (bx < 64) { in = Win;  oh = g_Wth; ol = g_Wtl; N = 2048;  n0 = bx * 32; }
  else         { in = Wout; oh = g_Bth; ol = g_Btl; N = V_;    n0 = (bx - 64) * 32; }
  int tx = threadIdx.x, ty = threadIdx.y;
  int k0 = blockIdx.y * 32;
#pragma unroll
  for (int j = ty; j < 32; j += 8)
    tile[j][tx] = in[(size_t)(k0 + j) * N + n0 + tx];
  __syncthreads();
#pragma unroll
  for (int j = ty; j < 32; j += 8) {
    float v = tile[tx][j];
    size_t o = (size_t)(n0 + j) * 512 + k0 + tx;
    split_bf16(v, &oh[o], &ol[o]);
  }
}

// embedding + inline word dropout -> bf16 hi/lo A operand directly
__global__ void embed_kernel(const float* __restrict__ images_emb,
                             const void* __restrict__ targets,
                             const float* __restrict__ emb_table,
                             uint32_t k1a, uint32_t k1b) {
  int idx = blockIdx.x * blockDim.x + threadIdx.x;        // 1048576
  int e = idx & 511, t = (idx >> 9) & 63, b = idx >> 15;
  float v;
  if (t == 0) {
    v = images_emb[b*E_ + e];
  } else {
    int w;
    if (g_is64) w = (int)((const long long*)targets)[b*L_ + (t-1)];
    else        w = ((const int*)targets)[b*L_ + (t-1)];
    v = emb_table[(size_t)w * E_ + e] * bern_val(k1a, k1b, (uint32_t)(b*E_ + e));
  }
  split_bf16(v, &g_Ah[idx], &g_Al[idx]);
}

// ---------------- LSTM step (one launch per timestep) ----------------
// 128 blocks x 256 threads; block owns v in [4*bid, 4*bid+4).
// Thread (q, b): q = pair p (v-pair) x u-quarter uq; computes 2v x 4gates over 128 u.
// smem tree-reduce across the 4 u-quarters, 64 threads finish the gate math.
__global__ __launch_bounds__(256) void lstm_step_kernel(int t, int pp) {
  __shared__ float4 ws[2048];       // [u][vloc] : 32KB
  __shared__ float4 sp[512];        // partials [slot=q*2+v2][b] : 8KB

  const float4* __restrict__ hin  = pp ? g_hmB : g_hmA;
  float4* __restrict__       hout = pp ? g_hmA : g_hmB;

  int tid = threadIdx.x, b = tid & 31, q = tid >> 5;
  int p = q & 1, uq = q >> 1;
  int vbase = blockIdx.x << 2;

  for (int i = tid; i < 2048; i += 256) {
    int u = i >> 2, vl = i & 3;
    ws[i] = g_Wr4[u*512 + vbase + vl];
  }
  __syncthreads();

  float4 a0 = make_float4(0.f, 0.f, 0.f, 0.f);
  float4 a1 = make_float4(0.f, 0.f, 0.f, 0.f);
  {
    int u0 = uq << 7;
    const float4* hp = hin + u0*32 + b;
    const float4* wp = ws + u0*4 + p*2;
#pragma unroll 8
    for (int u = 0; u < 128; u++) {
      float4 h4 = hp[u*32];
      float4 w0 = wp[u*4];
      float4 w1 = wp[u*4 + 1];
      a0.x = fmaf(h4.x, w0.x, a0.x); a0.y = fmaf(h4.y, w0.y, a0.y);
      a0.z = fmaf(h4.z, w0.z, a0.z); a0.w = fmaf(h4.w, w0.w, a0.w);
      a1.x = fmaf(h4.x, w1.x, a1.x); a1.y = fmaf(h4.y, w1.y, a1.y);
      a1.z = fmaf(h4.z, w1.z, a1.z); a1.w = fmaf(h4.w, w1.w, a1.w);
    }
  }
  sp[(q*2 + 0)*32 + b] = a0;
  sp[(q*2 + 1)*32 + b] = a1;
  __syncthreads();

  if (q < 2) {
#pragma unroll
    for (int v2 = 0; v2 < 2; v2++) {
      int slot = q*2 + v2;
      float4 a = sp[slot*32 + b];
      float4 s1 = sp[(slot + 4)*32 + b];
      float4 s2 = sp[(slot + 8)*32 + b];
      float4 s3 = sp[(slot + 12)*32 + b];
      a.x += s1.x + s2.x + s3.x;
      a.y += s1.y + s2.y + s3.y;
      a.z += s1.z + s2.z + s3.z;
      a.w += s1.w + s2.w + s3.w;

      int v = vbase + slot;           // p == q here, vloc = q*2+v2 = slot
      int row = (b << 6) + t;
      const float* zr = g_zin + (size_t)row * 2048 + v;
      float zi = zr[0]    + a.x;
      float zf = zr[512]  + a.y;
      float zg = zr[1024] + a.z;
      float zo = zr[1536] + a.w;

      float ig = 1.f / (1.f + expf(-zi));
      float fg = 1.f / (1.f + expf(-zf));
      float gv = tanhf(zg);
      float og = 1.f / (1.f + expf(-zo));

      int ci = v*32 + b;
      float cn = fmaf(fg, g_c[ci], ig * gv);
      g_c[ci] = cn;
      float hn = og * tanhf(cn);

      int ro = row*512 + v;
      float rv = hn * g_fin[ro];
      split_bf16(rv, &g_Ah[ro], &g_Al[ro]);

      float4 mm = g_rm4[ci];
      hout[ci] = make_float4(hn*mm.x, hn*mm.y, hn*mm.z, hn*mm.w);
    }
  }
}

// ---------------- HMMA (mma.sync) bf16x3 GEMM, 4-stage cp.async ----------------
// C[2048, Ntot] = (Ah+Al)[2048,512] @ (Bh+Bl)[Ntot,512]^T + bias
// CTA tile 128x128, 8 warps (2M x 4N), warp tile 64x32, BK=32.

__device__ __forceinline__ uint32_t smem_u32(const void* p) {
  uint32_t a;
  asm("{ .reg .u64 t; cvta.to.shared.u64 t, %1; cvt.u32.u64 %0, t; }" : "=r"(a) : "l"(p));
  return a;
}
__device__ __forceinline__ void cp16(uint32_t dst, const void* src) {
  asm volatile("cp.async.cg.shared.global [%0], [%1], 16;" :: "r"(dst), "l"(src));
}
#define LDSM4(d, a) asm volatile( \
  "ldmatrix.sync.aligned.m8n8.x4.shared.b16 {%0,%1,%2,%3}, [%4];" \
  : "=r"((d)[0]), "=r"((d)[1]), "=r"((d)[2]), "=r"((d)[3]) : "r"(a))
#define LDSM2(d, a) asm volatile( \
  "ldmatrix.sync.aligned.m8n8.x2.shared.b16 {%0,%1}, [%2];" \
  : "=r"((d)[0]), "=r"((d)[1]) : "r"(a))
#define MMA16816(ac, af, bf) asm volatile( \
  "mma.sync.aligned.m16n8k16.row.col.f32.bf16.bf16.f32 " \
  "{%0,%1,%2,%3}, {%4,%5,%6,%7}, {%8,%9}, {%0,%1,%2,%3};" \
  : "+f"((ac)[0]), "+f"((ac)[1]), "+f"((ac)[2]), "+f"((ac)[3]) \
  : "r"((af)[0]), "r"((af)[1]), "r"((af)[2]), "r"((af)[3]), \
    "r"((bf)[0]), "r"((bf)[1]))

#define TPB 10240
#define STG 40960
#define OFF_AH 0
#define OFF_AL TPB
#define OFF_BH (2*TPB)
#define OFF_BL (3*TPB)
#define GEMM_SMEM (4*STG)   // 4 stages = 160KB

__global__ __launch_bounds__(256) void gemm_mma_kernel(
    const __nv_bfloat16* __restrict__ Ah, const __nv_bfloat16* __restrict__ Al,
    const __nv_bfloat16* __restrict__ Bh, const __nv_bfloat16* __restrict__ Bl,
    const float* __restrict__ bias, float* __restrict__ C, int Ntot)
{
  extern __shared__ char smem[];
  uint32_t sb = smem_u32(smem);
  int tid = threadIdx.x, wid = tid >> 5, lane = tid & 31;
  int wm = wid >> 2, wn = wid & 3;
  int M0 = blockIdx.y << 7, N0 = blockIdx.x << 7;

  int r0 = tid >> 2, c0 = (tid & 3);
  uint32_t ld_d0 = (uint32_t)r0 * 80u + (uint32_t)c0 * 16u;
  uint32_t ld_d1 = (uint32_t)(r0 + 64) * 80u + (uint32_t)c0 * 16u;

  uint32_t aBase = (uint32_t)((wm << 6) + (lane & 7) + (((lane >> 3) & 1) << 3)) * 80u
                 + (uint32_t)((lane >> 4) << 4);
  uint32_t bBase = (uint32_t)(((wn << 5) + (lane & 7))) * 80u
                 + (uint32_t)(((lane >> 3) & 1) << 4);

  float acc[4][4][4];
#pragma unroll
  for (int i = 0; i < 4; i++)
#pragma unroll
    for (int j = 0; j < 4; j++)
#pragma unroll
      for (int q = 0; q < 4; q++) acc[i][j][q] = 0.f;

  // prologue: prefetch stages 0..2
#pragma unroll
  for (int ps = 0; ps < 3; ps++) {
    uint32_t s1 = sb + (uint32_t)ps * STG;
    int kk = ps * 32;
    size_t gA0 = (size_t)(M0 + r0) * 512 + kk + c0 * 8;
    size_t gA1 = (size_t)(M0 + r0 + 64) * 512 + kk + c0 * 8;
    size_t gB0 = (size_t)(N0 + r0) * 512 + kk + c0 * 8;
    size_t gB1 = (size_t)(N0 + r0 + 64) * 512 + kk + c0 * 8;
    cp16(s1 + OFF_AH + ld_d0, Ah + gA0); cp16(s1 + OFF_AH + ld_d1, Ah + gA1);
    cp16(s1 + OFF_AL + ld_d0, Al + gA0); cp16(s1 + OFF_AL + ld_d1, Al + gA1);
    cp16(s1 + OFF_BH + ld_d0, Bh + gB0); cp16(s1 + OFF_BH + ld_d1, Bh + gB1);
    cp16(s1 + OFF_BL + ld_d0, Bl + gB0); cp16(s1 + OFF_BL + ld_d1, Bl + gB1);
    asm volatile("cp.async.commit_group;" ::: "memory");
  }

  for (int kc = 0; kc < 16; kc++) {
    asm volatile("cp.async.wait_group 2;" ::: "memory");
    __syncthreads();
    if (kc + 3 < 16) {
      uint32_t s1 = sb + (uint32_t)((kc + 3) & 3) * STG;
      int kk = (kc + 3) * 32;
      size_t gA0 = (size_t)(M0 + r0) * 512 + kk + c0 * 8;
      size_t gA1 = (size_t)(M0 + r0 + 64) * 512 + kk + c0 * 8;
      size_t gB0 = (size_t)(N0 + r0) * 512 + kk + c0 * 8;
      size_t gB1 = (size_t)(N0 + r0 + 64) * 512 + kk + c0 * 8;
      cp16(s1 + OFF_AH + ld_d0, Ah + gA0); cp16(s1 + OFF_AH + ld_d1, Ah + gA1);
      cp16(s1 + OFF_AL + ld_d0, Al + gA0); cp16(s1 + OFF_AL + ld_d1, Al + gA1);
      cp16(s1 + OFF_BH + ld_d0, Bh + gB0); cp16(s1 + OFF_BH + ld_d1, Bh + gB1);
      cp16(s1 + OFF_BL + ld_d0, Bl + gB0); cp16(s1 + OFF_BL + ld_d1, Bl + gB1);
      asm volatile("cp.async.commit_group;" ::: "memory");
    } else {
      asm volatile("cp.async.commit_group;" ::: "memory");
    }

    uint32_t s0 = sb + (uint32_t)(kc & 3) * STG;
#pragma unroll
    for (int ks = 0; ks < 2; ks++) {
      uint32_t bh[4][2], bl[4][2];
#pragma unroll
      for (int nt = 0; nt < 4; nt++) {
        uint32_t bo = bBase + (uint32_t)(nt * 640 + ks * 32);
        LDSM2(bh[nt], s0 + OFF_BH + bo);
        LDSM2(bl[nt], s0 + OFF_BL + bo);
      }
#pragma unroll
      for (int mt = 0; mt < 4; mt++) {
        uint32_t ah[4], al[4];
        uint32_t ao = aBase + (uint32_t)(mt * 1280 + ks * 32);
        LDSM4(ah, s0 + OFF_AH + ao);
        LDSM4(al, s0 + OFF_AL + ao);
#pragma unroll
        for (int nt = 0; nt < 4; nt++) MMA16816(acc[mt][nt], ah, bh[nt]);
#pragma unroll
        for (int nt = 0; nt < 4; nt++) MMA16816(acc[mt][nt], ah, bl[nt]);
#pragma unroll
        for (int nt = 0; nt < 4; nt++) MMA16816(acc[mt][nt], al, bh[nt]);
      }
    }
    __syncthreads();
  }

  // epilogue
#pragma unroll
  for (int mt = 0; mt < 4; mt++) {
    int grow = M0 + (wm << 6) + mt * 16 + (lane >> 2);
#pragma unroll
    for (int nt = 0; nt < 4; nt++) {
      int gcol = N0 + (wn << 5) + nt * 8 + (lane & 3) * 2;
      float bx = __ldg(&bias[gcol]), by = __ldg(&bias[gcol + 1]);
      float2 o0 = make_float2(acc[mt][nt][0] + bx, acc[mt][nt][1] + by);
      float2 o1 = make_float2(acc[mt][nt][2] + bx, acc[mt][nt][3] + by);
      *(float2*)&C[(size_t)grow * Ntot + gcol] = o0;
      *(float2*)&C[(size_t)(grow + 8) * Ntot + gcol] = o1;
    }
  }
}

// ---------------- host ----------------
extern "C" void kernel_launch(void* const* d_in, const int* in_sizes, int n_in,
                              void* d_out, int out_size) {
  (void)in_sizes; (void)n_in; (void)out_size;
  const float* images_emb = (const float*)d_in[1];
  const void*  targets    = d_in[2];
  const float* emb_table  = (const float*)d_in[3];
  const float* W_in       = (const float*)d_in[4];
  const float* W_rec      = (const float*)d_in[5];
  const float* b_lstm     = (const float*)d_in[6];
  const float* W_out      = (const float*)d_in[7];
  const float* b_out      = (const float*)d_in[8];
  float* out = (float*)d_out;

  void *pzin = nullptr, *pah = nullptr, *pal = nullptr, *pbth = nullptr,
       *pbtl = nullptr, *pwth = nullptr, *pwtl = nullptr;
  cudaGetSymbolAddress(&pzin, g_zin);
  cudaGetSymbolAddress(&pah,  g_Ah);
  cudaGetSymbolAddress(&pal,  g_Al);
  cudaGetSymbolAddress(&pbth, g_Bth);
  cudaGetSymbolAddress(&pbtl, g_Btl);
  cudaGetSymbolAddress(&pwth, g_Wth);
  cudaGetSymbolAddress(&pwtl, g_Wtl);

  cudaFuncSetAttribute(gemm_mma_kernel,
                       cudaFuncAttributeMaxDynamicSharedMemorySize, GEMM_SMEM);

  uint32_t k1a, k1b, k2a, k2b, k3a, k3b;
  tf2x32(0u, 42u, 0u, 0u, &k1a, &k1b);
  tf2x32(0u, 42u, 0u, 1u, &k2a, &k2b);
  tf2x32(0u, 42u, 0u, 2u, &k3a, &k3b);

  // launch order tuned so gemm_mma (zin) is my launch index 3 for ncu capture
  masks_kernel<<<4096, 256>>>(k2a, k2b, k3a, k3b, W_rec, (const int*)targets);
  transpose_split_kernel<<<dim3(1064, 16), dim3(32, 8)>>>(W_in, W_out);
  embed_kernel<<<4096, 256>>>(images_emb, targets, emb_table, k1a, k1b);

  // z_in = x @ W_in + b_lstm   [2048, 2048]
  gemm_mma_kernel<<<dim3(16, 16), 256, GEMM_SMEM>>>(
      (const __nv_bfloat16*)pah, (const __nv_bfloat16*)pal,
      (const __nv_bfloat16*)pwth, (const __nv_bfloat16*)pwtl,
      b_lstm, (float*)pzin, 2048);

  // recurrence: 64 per-step launches (graph-captured)
  for (int t = 0; t < 64; t++)
    lstm_step_kernel<<<128, 256>>>(t, t & 1);

  // predictions = rnn_out @ W_out + b_out   [2048, 32000]
  gemm_mma_kernel<<<dim3(250, 16), 256, GEMM_SMEM>>>(
      (const __nv_bfloat16*)pah, (const __nv_bfloat16*)pal,
      (const __nv_bfloat16*)pbth, (const __nv_bfloat16*)pbtl,
      b_out, out, V_);
}